// round 16
// baseline (speedup 1.0000x reference)
#include <cuda_runtime.h>
#include <cuda_bf16.h>
#include <cstdint>

#define BB 512
#define NN 2048
#define FF 64
#define H1 64
#define H2 32
#define BT 128
#define NTILE (BB / BT)   // 4 batch tiles per persistent CTA
#define THREADS 128
#define XP 72             // padded row length in bf16 elems (144 B)
#define XPB 144           // row bytes

struct Smem {
    __nv_bfloat16 Xs[BT][XP];    // x tile (bf16); warp-private row slices
    __nv_bfloat16 W0s[H1][XP];   // W0[t] rows: [out][in]
    __nv_bfloat16 W1s[H2][XP];   // W1[t] rows: [out][in]
    float b0s[H1];
    float b1s[H2];
    float w2s[H2];
    float b2s;
};

static __device__ __forceinline__ uint32_t smem_u32(const void* p) {
    uint32_t a;
    asm("{ .reg .u64 t; cvta.to.shared.u64 t, %1; cvt.u32.u64 %0, t; }" : "=r"(a) : "l"(p));
    return a;
}
static __device__ __forceinline__ uint32_t pkbf(float lo, float hi) {
    uint32_t r; asm("cvt.rn.bf16x2.f32 %0, %1, %2;" : "=r"(r) : "f"(hi), "f"(lo));
    return r;
}
static __device__ __forceinline__ float silu_t(float v) {
    float t; asm("tanh.approx.f32 %0, %1;" : "=f"(t) : "f"(0.5f * v));
    return 0.5f * v * (1.0f + t);
}
static __device__ __forceinline__ void ldsm4(uint32_t* r, uint32_t addr) {
    asm volatile("ldmatrix.sync.aligned.m8n8.x4.shared.b16 {%0,%1,%2,%3}, [%4];"
                 : "=r"(r[0]), "=r"(r[1]), "=r"(r[2]), "=r"(r[3]) : "r"(addr));
}
static __device__ __forceinline__ void mma16(float* d, const uint32_t* a,
                                             uint32_t b0r_, uint32_t b1r_) {
    asm volatile(
        "mma.sync.aligned.m16n8k16.row.col.f32.bf16.bf16.f32 "
        "{%0,%1,%2,%3}, {%4,%5,%6,%7}, {%8,%9}, {%0,%1,%2,%3};"
        : "+f"(d[0]), "+f"(d[1]), "+f"(d[2]), "+f"(d[3])
        : "r"(a[0]), "r"(a[1]), "r"(a[2]), "r"(a[3]), "r"(b0r_), "r"(b1r_));
}

__global__ void zero_out_kernel(float* __restrict__ out) {
    out[threadIdx.x] = 0.0f;
}

__global__ __launch_bounds__(THREADS, 4)
void bpnn_bf16_kernel(const float* __restrict__ x,
                      const int*   __restrict__ atomic_numbers,
                      const float* __restrict__ w0, const float* __restrict__ b0,
                      const float* __restrict__ w1, const float* __restrict__ b1,
                      const float* __restrict__ w2, const float* __restrict__ b2,
                      float* __restrict__ out)
{
    extern __shared__ char smem_raw[];
    Smem& s = *reinterpret_cast<Smem*>(smem_raw);

    const int tid = threadIdx.x;
    const int wid = tid >> 5;
    const int lid = tid & 31;
    const int gid = lid >> 2;
    const int tig = lid & 3;
    const int n   = blockIdx.x;       // one atom per CTA, persistent over batch

    const int t = atomic_numbers[n];
    const int r0 = wid * 32;          // warp-private 32-row slice

    const int q  = lid & 15;          // staging lane geometry
    const int rh = lid >> 4;
    const size_t stride2 = (size_t)2 * NN * FF;       // 2 rows
    const size_t tileStride = (size_t)BT * NN * FF;   // 128 rows
    const size_t gBase = ((size_t)(r0 + rh) * NN + n) * FF + q * 4;

    float4 xva[8], xvb[8];

    // ---- prologue: fire tile 0's LDGs (both halves), then weights ----
    {
        size_t g = gBase;
        #pragma unroll
        for (int it = 0; it < 8; ++it) { xva[it] = *reinterpret_cast<const float4*>(&x[g]); g += stride2; }
        #pragma unroll
        for (int it = 0; it < 8; ++it) { xvb[it] = *reinterpret_cast<const float4*>(&x[g]); g += stride2; }
    }
    {
        const float* w0p = w0 + t * H1 * FF;
        #pragma unroll
        for (int it = 0; it < 8; ++it) {
            int task = it * THREADS + tid;
            int row = task >> 4, qq = task & 15;
            float4 v = *reinterpret_cast<const float4*>(&w0p[row * FF + qq * 4]);
            uint2 o = make_uint2(pkbf(v.x, v.y), pkbf(v.z, v.w));
            *reinterpret_cast<uint2*>(&s.W0s[row][qq * 4]) = o;
        }
        const float* w1p = w1 + t * H2 * H1;
        #pragma unroll
        for (int it = 0; it < 4; ++it) {
            int task = it * THREADS + tid;
            int row = task >> 4, qq = task & 15;
            float4 v = *reinterpret_cast<const float4*>(&w1p[row * H1 + qq * 4]);
            uint2 o = make_uint2(pkbf(v.x, v.y), pkbf(v.z, v.w));
            *reinterpret_cast<uint2*>(&s.W1s[row][qq * 4]) = o;
        }
        if (tid < H1) s.b0s[tid] = b0[t * H1 + tid];
        if (tid < H2) { s.b1s[tid] = b1[t * H2 + tid]; s.w2s[tid] = w2[t * H2 + tid]; }
        if (tid == 0) s.b2s = b2[t];
    }
    // commit half-A of tile 0 (rows r0..r0+15) before the barrier
    #pragma unroll
    for (int it = 0; it < 8; ++it) {
        int row = r0 + it * 2 + rh;
        uint2 o = make_uint2(pkbf(xva[it].x, xva[it].y), pkbf(xva[it].z, xva[it].w));
        *reinterpret_cast<uint2*>(&s.Xs[row][q * 4]) = o;
    }
    __syncthreads();   // only CTA barrier in the whole kernel

    // ldmatrix base addresses (constant across tiles)
    const uint32_t aBase = smem_u32(&s.Xs[0][0]) +
        (uint32_t)(r0 + (lid & 15)) * XPB + (uint32_t)((lid >> 4) * 8) * 2;
    const uint32_t bRow = (lid & 7) + ((lid >> 4) << 3);
    const uint32_t bColB = (((lid >> 3) & 1) * 8) * 2;
    const uint32_t b0Base = smem_u32(&s.W0s[0][0]) + bRow * XPB + bColB;
    const uint32_t b1Base = smem_u32(&s.W1s[0][0]) + bRow * XPB + bColB;

    #pragma unroll 1
    for (int bt = 0; bt < NTILE; ++bt) {
        // ---- commit half-B of current tile (rows r0+16..r0+31) ----
        #pragma unroll
        for (int it = 0; it < 8; ++it) {
            int row = r0 + 16 + it * 2 + rh;
            uint2 o = make_uint2(pkbf(xvb[it].x, xvb[it].y), pkbf(xvb[it].z, xvb[it].w));
            *reinterpret_cast<uint2*>(&s.Xs[row][q * 4]) = o;
        }
        __syncwarp();

        // ================= GEMM1: D1[32x64] = X . W0^T =================
        float acc[2][8][4];
        #pragma unroll
        for (int mt = 0; mt < 2; ++mt)
            #pragma unroll
            for (int nt = 0; nt < 8; ++nt)
                #pragma unroll
                for (int c = 0; c < 4; ++c) acc[mt][nt][c] = 0.0f;

        #pragma unroll
        for (int kt = 0; kt < 2; ++kt) {
            uint32_t a[2][4];
            ldsm4(a[0], aBase + kt * 32);
            ldsm4(a[1], aBase + 16 * XPB + kt * 32);
            #pragma unroll
            for (int np = 0; np < 4; ++np) {
                uint32_t bfr[4];
                ldsm4(bfr, b0Base + np * 16 * XPB + kt * 32);
                mma16(acc[0][2 * np    ], a[0], bfr[0], bfr[1]);
                mma16(acc[0][2 * np + 1], a[0], bfr[2], bfr[3]);
                mma16(acc[1][2 * np    ], a[1], bfr[0], bfr[1]);
                mma16(acc[1][2 * np + 1], a[1], bfr[2], bfr[3]);
            }
        }

        // ---- load half-A of NEXT tile (rows r0..r0+15) during GEMM1 tail ----
        if (bt + 1 < NTILE) {
            size_t g = gBase + (size_t)(bt + 1) * tileStride;
            #pragma unroll
            for (int it = 0; it < 8; ++it) { xva[it] = *reinterpret_cast<const float4*>(&x[g]); g += stride2; }
        }

        #pragma unroll
        for (int kt = 2; kt < 4; ++kt) {
            uint32_t a[2][4];
            ldsm4(a[0], aBase + kt * 32);
            ldsm4(a[1], aBase + 16 * XPB + kt * 32);
            #pragma unroll
            for (int np = 0; np < 4; ++np) {
                uint32_t bfr[4];
                ldsm4(bfr, b0Base + np * 16 * XPB + kt * 32);
                mma16(acc[0][2 * np    ], a[0], bfr[0], bfr[1]);
                mma16(acc[0][2 * np + 1], a[0], bfr[2], bfr[3]);
                mma16(acc[1][2 * np    ], a[1], bfr[0], bfr[1]);
                mma16(acc[1][2 * np + 1], a[1], bfr[2], bfr[3]);
            }
        }

        // ---- epilogue 1 (register-resident): GEMM2 A-fragments directly ----
        uint32_t h1f[2][4][4];
        #pragma unroll
        for (int mt = 0; mt < 2; ++mt) {
            #pragma unroll
            for (int kt2 = 0; kt2 < 4; ++kt2) {
                int cA = kt2 * 16 + 2 * tig;
                int cB = cA + 8;
                float bA0 = s.b0s[cA], bA1 = s.b0s[cA + 1];
                float bB0 = s.b0s[cB], bB1 = s.b0s[cB + 1];
                const float* dA = acc[mt][2 * kt2];
                const float* dB = acc[mt][2 * kt2 + 1];
                h1f[mt][kt2][0] = pkbf(silu_t(dA[0] + bA0), silu_t(dA[1] + bA1));
                h1f[mt][kt2][1] = pkbf(silu_t(dA[2] + bA0), silu_t(dA[3] + bA1));
                h1f[mt][kt2][2] = pkbf(silu_t(dB[0] + bB0), silu_t(dB[1] + bB1));
                h1f[mt][kt2][3] = pkbf(silu_t(dB[2] + bB0), silu_t(dB[3] + bB1));
            }
        }

        // ---- commit half-A of NEXT tile (current X fully consumed; acc dead) ----
        if (bt + 1 < NTILE) {
            #pragma unroll
            for (int it = 0; it < 8; ++it) {
                int row = r0 + it * 2 + rh;
                uint2 o = make_uint2(pkbf(xva[it].x, xva[it].y), pkbf(xva[it].z, xva[it].w));
                *reinterpret_cast<uint2*>(&s.Xs[row][q * 4]) = o;
            }
        }

        // ---- load half-B of NEXT tile (overlaps GEMM2) ----
        if (bt + 1 < NTILE) {
            size_t g = gBase + (size_t)(bt + 1) * tileStride + 16 * (size_t)NN * FF;
            #pragma unroll
            for (int it = 0; it < 8; ++it) { xvb[it] = *reinterpret_cast<const float4*>(&x[g]); g += stride2; }
        }

        // ================= GEMM2: D2[32x32] = H1 . W1^T (A from regs) =================
        float acc2[2][4][4];
        #pragma unroll
        for (int mt = 0; mt < 2; ++mt)
            #pragma unroll
            for (int nt = 0; nt < 4; ++nt)
                #pragma unroll
                for (int c = 0; c < 4; ++c) acc2[mt][nt][c] = 0.0f;

        #pragma unroll
        for (int kt2 = 0; kt2 < 4; ++kt2) {
            #pragma unroll
            for (int np = 0; np < 2; ++np) {
                uint32_t bfr[4];
                ldsm4(bfr, b1Base + np * 16 * XPB + kt2 * 32);
                mma16(acc2[0][2 * np    ], h1f[0][kt2], bfr[0], bfr[1]);
                mma16(acc2[0][2 * np + 1], h1f[0][kt2], bfr[2], bfr[3]);
                mma16(acc2[1][2 * np    ], h1f[1][kt2], bfr[0], bfr[1]);
                mma16(acc2[1][2 * np + 1], h1f[1][kt2], bfr[2], bfr[3]);
            }
        }

        // ---- epilogue 2: e[row] = b2 + sum_c w2[c]*silu(D2[row][c]+b1[c]) ----
        {
            float b1r[4][2], w2r[4][2];
            #pragma unroll
            for (int nt = 0; nt < 4; ++nt) {
                int c0 = nt * 8 + 2 * tig;
                b1r[nt][0] = s.b1s[c0]; b1r[nt][1] = s.b1s[c0 + 1];
                w2r[nt][0] = s.w2s[c0]; w2r[nt][1] = s.w2s[c0 + 1];
            }
            const float bb2 = s.b2s;

            #pragma unroll
            for (int mt = 0; mt < 2; ++mt) {
                float elo = 0.0f, ehi = 0.0f;
                #pragma unroll
                for (int nt = 0; nt < 4; ++nt) {
                    elo += w2r[nt][0] * silu_t(acc2[mt][nt][0] + b1r[nt][0]);
                    elo += w2r[nt][1] * silu_t(acc2[mt][nt][1] + b1r[nt][1]);
                    ehi += w2r[nt][0] * silu_t(acc2[mt][nt][2] + b1r[nt][0]);
                    ehi += w2r[nt][1] * silu_t(acc2[mt][nt][3] + b1r[nt][1]);
                }
                #pragma unroll
                for (int off = 1; off < 4; off <<= 1) {
                    elo += __shfl_xor_sync(0xffffffffu, elo, off);
                    ehi += __shfl_xor_sync(0xffffffffu, ehi, off);
                }
                if (tig == 0) {
                    int rlo = bt * BT + r0 + mt * 16 + gid;
                    atomicAdd(&out[rlo],     elo + bb2);
                    atomicAdd(&out[rlo + 8], ehi + bb2);
                }
            }
        }
        // no CTA barrier: Xs rows are warp-private, weights read-only
    }
}

extern "C" void kernel_launch(void* const* d_in, const int* in_sizes, int n_in,
                              void* d_out, int out_size)
{
    const float* x  = (const float*)d_in[0];
    const int*   an = (const int*)  d_in[1];
    const float* w0 = (const float*)d_in[2];
    const float* b0 = (const float*)d_in[3];
    const float* w1 = (const float*)d_in[4];
    const float* b1 = (const float*)d_in[5];
    const float* w2 = (const float*)d_in[6];
    const float* b2 = (const float*)d_in[7];
    float* out = (float*)d_out;

    static_assert(sizeof(Smem) < 48 * 1024, "smem too big");
    cudaFuncSetAttribute(bpnn_bf16_kernel,
                         cudaFuncAttributeMaxDynamicSharedMemorySize,
                         (int)sizeof(Smem));

    zero_out_kernel<<<1, BB>>>(out);

    bpnn_bf16_kernel<<<NN, THREADS, sizeof(Smem)>>>(x, an, w0, b0, w1, b1, w2, b2, out);
}

// round 17
// speedup vs baseline: 1.4710x; 1.4710x over previous
#include <cuda_runtime.h>
#include <cuda_bf16.h>
#include <cstdint>

#define BB 512
#define NN 2048
#define FF 64
#define H1 64
#define H2 32
#define BT 128
#define NTILE (BB / BT)   // 4 batch tiles per persistent CTA
#define THREADS 128
#define XP 72             // padded row length in bf16 elems (144 B)
#define XPB 144           // row bytes

struct Smem {
    __nv_bfloat16 Xs[BT][XP];    // x tile (bf16); warp-private row slices
    __nv_bfloat16 W0s[H1][XP];   // W0[t] rows: [out][in]
    __nv_bfloat16 W1s[H2][XP];   // W1[t] rows: [out][in]
    float b0s[H1];
    float b1s[H2];
    float w2s[H2];
    float b2s;
};

static __device__ __forceinline__ uint32_t smem_u32(const void* p) {
    uint32_t a;
    asm("{ .reg .u64 t; cvta.to.shared.u64 t, %1; cvt.u32.u64 %0, t; }" : "=r"(a) : "l"(p));
    return a;
}
static __device__ __forceinline__ uint32_t pkbf(float lo, float hi) {
    uint32_t r; asm("cvt.rn.bf16x2.f32 %0, %1, %2;" : "=r"(r) : "f"(hi), "f"(lo));
    return r;
}
static __device__ __forceinline__ float silu_t(float v) {
    float t; asm("tanh.approx.f32 %0, %1;" : "=f"(t) : "f"(0.5f * v));
    return 0.5f * v * (1.0f + t);
}
static __device__ __forceinline__ void ldsm4(uint32_t* r, uint32_t addr) {
    asm volatile("ldmatrix.sync.aligned.m8n8.x4.shared.b16 {%0,%1,%2,%3}, [%4];"
                 : "=r"(r[0]), "=r"(r[1]), "=r"(r[2]), "=r"(r[3]) : "r"(addr));
}
static __device__ __forceinline__ void mma16(float* d, const uint32_t* a,
                                             uint32_t b0r_, uint32_t b1r_) {
    asm volatile(
        "mma.sync.aligned.m16n8k16.row.col.f32.bf16.bf16.f32 "
        "{%0,%1,%2,%3}, {%4,%5,%6,%7}, {%8,%9}, {%0,%1,%2,%3};"
        : "+f"(d[0]), "+f"(d[1]), "+f"(d[2]), "+f"(d[3])
        : "r"(a[0]), "r"(a[1]), "r"(a[2]), "r"(a[3]), "r"(b0r_), "r"(b1r_));
}
static __device__ __forceinline__ void prefetchL2(const void* p) {
    asm volatile("prefetch.global.L2 [%0];" :: "l"(p));
}

__global__ void zero_out_kernel(float* __restrict__ out) {
    out[threadIdx.x] = 0.0f;
}

__global__ __launch_bounds__(THREADS)
void bpnn_bf16_kernel(const float* __restrict__ x,
                      const int*   __restrict__ atomic_numbers,
                      const float* __restrict__ w0, const float* __restrict__ b0,
                      const float* __restrict__ w1, const float* __restrict__ b1,
                      const float* __restrict__ w2, const float* __restrict__ b2,
                      float* __restrict__ out)
{
    extern __shared__ char smem_raw[];
    Smem& s = *reinterpret_cast<Smem*>(smem_raw);

    const int tid = threadIdx.x;
    const int wid = tid >> 5;
    const int lid = tid & 31;
    const int gid = lid >> 2;
    const int tig = lid & 3;
    const int n   = blockIdx.x;       // one atom per CTA, persistent over batch

    const int t = atomic_numbers[n];
    const int r0 = wid * 32;          // warp-private 32-row slice

    const int q  = lid & 15;          // staging lane geometry
    const int rh = lid >> 4;
    const size_t stride2 = (size_t)2 * NN * FF;       // 2 rows
    const size_t tileStride = (size_t)BT * NN * FF;   // 128 rows
    const size_t gBase = ((size_t)(r0 + rh) * NN + n) * FF + q * 4;

    // ---- prologue: fire tile 0's LDGs, stage weights under them, commit ----
    {
        float4 xv0[16];
        size_t g = gBase;
        #pragma unroll
        for (int it = 0; it < 16; ++it) {
            xv0[it] = *reinterpret_cast<const float4*>(&x[g]);
            g += stride2;
        }

        const float* w0p = w0 + t * H1 * FF;
        #pragma unroll
        for (int it = 0; it < 8; ++it) {
            int task = it * THREADS + tid;
            int row = task >> 4, qq = task & 15;
            float4 v = *reinterpret_cast<const float4*>(&w0p[row * FF + qq * 4]);
            uint2 o = make_uint2(pkbf(v.x, v.y), pkbf(v.z, v.w));
            *reinterpret_cast<uint2*>(&s.W0s[row][qq * 4]) = o;
        }
        const float* w1p = w1 + t * H2 * H1;
        #pragma unroll
        for (int it = 0; it < 4; ++it) {
            int task = it * THREADS + tid;
            int row = task >> 4, qq = task & 15;
            float4 v = *reinterpret_cast<const float4*>(&w1p[row * H1 + qq * 4]);
            uint2 o = make_uint2(pkbf(v.x, v.y), pkbf(v.z, v.w));
            *reinterpret_cast<uint2*>(&s.W1s[row][qq * 4]) = o;
        }
        if (tid < H1) s.b0s[tid] = b0[t * H1 + tid];
        if (tid < H2) { s.b1s[tid] = b1[t * H2 + tid]; s.w2s[tid] = w2[t * H2 + tid]; }
        if (tid == 0) s.b2s = b2[t];

        // commit tile 0 (warp-private rows)
        #pragma unroll
        for (int it = 0; it < 16; ++it) {
            int row = r0 + it * 2 + rh;
            uint2 o = make_uint2(pkbf(xv0[it].x, xv0[it].y), pkbf(xv0[it].z, xv0[it].w));
            *reinterpret_cast<uint2*>(&s.Xs[row][q * 4]) = o;
        }
    }
    __syncthreads();   // only CTA barrier in the whole kernel

    // ldmatrix base addresses (constant across tiles)
    const uint32_t aBase = smem_u32(&s.Xs[0][0]) +
        (uint32_t)(r0 + (lid & 15)) * XPB + (uint32_t)((lid >> 4) * 8) * 2;
    const uint32_t bRow = (lid & 7) + ((lid >> 4) << 3);
    const uint32_t bColB = (((lid >> 3) & 1) * 8) * 2;
    const uint32_t b0Base = smem_u32(&s.W0s[0][0]) + bRow * XPB + bColB;
    const uint32_t b1Base = smem_u32(&s.W1s[0][0]) + bRow * XPB + bColB;

    #pragma unroll 1
    for (int bt = 0; bt < NTILE; ++bt) {
        // ================= GEMM1: D1[32x64] = X . W0^T =================
        // bias b0 folded into accumulator init (saves 64 FADD/thread)
        float acc[2][8][4];
        #pragma unroll
        for (int nt = 0; nt < 8; ++nt) {
            int c0 = nt * 8 + 2 * tig;
            float bv0 = s.b0s[c0], bv1 = s.b0s[c0 + 1];
            #pragma unroll
            for (int mt = 0; mt < 2; ++mt) {
                acc[mt][nt][0] = bv0; acc[mt][nt][1] = bv1;
                acc[mt][nt][2] = bv0; acc[mt][nt][3] = bv1;
            }
        }

        #pragma unroll
        for (int kt = 0; kt < 2; ++kt) {
            uint32_t a[2][4];
            ldsm4(a[0], aBase + kt * 32);
            ldsm4(a[1], aBase + 16 * XPB + kt * 32);
            #pragma unroll
            for (int np = 0; np < 4; ++np) {
                uint32_t bfr[4];
                ldsm4(bfr, b0Base + np * 16 * XPB + kt * 32);
                mma16(acc[0][2 * np    ], a[0], bfr[0], bfr[1]);
                mma16(acc[0][2 * np + 1], a[0], bfr[2], bfr[3]);
                mma16(acc[1][2 * np    ], a[1], bfr[0], bfr[1]);
                mma16(acc[1][2 * np + 1], a[1], bfr[2], bfr[3]);
            }
        }

        // ---- register-free L2 prefetch of NEXT tile (covers until loop bottom) ----
        if (bt + 1 < NTILE) {
            size_t g = gBase + (size_t)(bt + 1) * tileStride;
            #pragma unroll
            for (int it = 0; it < 16; ++it) {
                prefetchL2(&x[g]);
                g += stride2;
            }
        }

        #pragma unroll
        for (int kt = 2; kt < 4; ++kt) {
            uint32_t a[2][4];
            ldsm4(a[0], aBase + kt * 32);
            ldsm4(a[1], aBase + 16 * XPB + kt * 32);
            #pragma unroll
            for (int np = 0; np < 4; ++np) {
                uint32_t bfr[4];
                ldsm4(bfr, b0Base + np * 16 * XPB + kt * 32);
                mma16(acc[0][2 * np    ], a[0], bfr[0], bfr[1]);
                mma16(acc[0][2 * np + 1], a[0], bfr[2], bfr[3]);
                mma16(acc[1][2 * np    ], a[1], bfr[0], bfr[1]);
                mma16(acc[1][2 * np + 1], a[1], bfr[2], bfr[3]);
            }
        }

        // ---- epilogue 1 (register-resident): GEMM2 A-fragments directly ----
        uint32_t h1f[2][4][4];
        #pragma unroll
        for (int mt = 0; mt < 2; ++mt) {
            #pragma unroll
            for (int kt2 = 0; kt2 < 4; ++kt2) {
                const float* dA = acc[mt][2 * kt2];
                const float* dB = acc[mt][2 * kt2 + 1];
                h1f[mt][kt2][0] = pkbf(silu_t(dA[0]), silu_t(dA[1]));
                h1f[mt][kt2][1] = pkbf(silu_t(dA[2]), silu_t(dA[3]));
                h1f[mt][kt2][2] = pkbf(silu_t(dB[0]), silu_t(dB[1]));
                h1f[mt][kt2][3] = pkbf(silu_t(dB[2]), silu_t(dB[3]));
            }
        }

        // ================= GEMM2: D2[32x32] = H1 . W1^T (A from regs) =================
        // bias b1 folded into accumulator init
        float acc2[2][4][4];
        #pragma unroll
        for (int nt = 0; nt < 4; ++nt) {
            int c0 = nt * 8 + 2 * tig;
            float bv0 = s.b1s[c0], bv1 = s.b1s[c0 + 1];
            #pragma unroll
            for (int mt = 0; mt < 2; ++mt) {
                acc2[mt][nt][0] = bv0; acc2[mt][nt][1] = bv1;
                acc2[mt][nt][2] = bv0; acc2[mt][nt][3] = bv1;
            }
        }

        #pragma unroll
        for (int kt2 = 0; kt2 < 4; ++kt2) {
            #pragma unroll
            for (int np = 0; np < 2; ++np) {
                uint32_t bfr[4];
                ldsm4(bfr, b1Base + np * 16 * XPB + kt2 * 32);
                mma16(acc2[0][2 * np    ], h1f[0][kt2], bfr[0], bfr[1]);
                mma16(acc2[0][2 * np + 1], h1f[0][kt2], bfr[2], bfr[3]);
                mma16(acc2[1][2 * np    ], h1f[1][kt2], bfr[0], bfr[1]);
                mma16(acc2[1][2 * np + 1], h1f[1][kt2], bfr[2], bfr[3]);
            }
        }

        // ---- epilogue 2: e[row] = b2 + sum_c w2[c]*silu(D2[row][c]) ----
        {
            float w2r[4][2];
            #pragma unroll
            for (int nt = 0; nt < 4; ++nt) {
                int c0 = nt * 8 + 2 * tig;
                w2r[nt][0] = s.w2s[c0]; w2r[nt][1] = s.w2s[c0 + 1];
            }
            const float bb2 = s.b2s;

            #pragma unroll
            for (int mt = 0; mt < 2; ++mt) {
                float elo = 0.0f, ehi = 0.0f;
                #pragma unroll
                for (int nt = 0; nt < 4; ++nt) {
                    elo += w2r[nt][0] * silu_t(acc2[mt][nt][0]);
                    elo += w2r[nt][1] * silu_t(acc2[mt][nt][1]);
                    ehi += w2r[nt][0] * silu_t(acc2[mt][nt][2]);
                    ehi += w2r[nt][1] * silu_t(acc2[mt][nt][3]);
                }
                #pragma unroll
                for (int off = 1; off < 4; off <<= 1) {
                    elo += __shfl_xor_sync(0xffffffffu, elo, off);
                    ehi += __shfl_xor_sync(0xffffffffu, ehi, off);
                }
                if (tig == 0) {
                    int rlo = bt * BT + r0 + mt * 16 + gid;
                    atomicAdd(&out[rlo],     elo + bb2);
                    atomicAdd(&out[rlo + 8], ehi + bb2);
                }
            }
        }

        // ---- stage NEXT tile at loop bottom (LDGs hit L2 via prefetch) ----
        if (bt + 1 < NTILE) {
            size_t g = gBase + (size_t)(bt + 1) * tileStride;
            #pragma unroll
            for (int it = 0; it < 16; ++it) {
                float4 v = *reinterpret_cast<const float4*>(&x[g]);
                g += stride2;
                int row = r0 + it * 2 + rh;
                uint2 o = make_uint2(pkbf(v.x, v.y), pkbf(v.z, v.w));
                *reinterpret_cast<uint2*>(&s.Xs[row][q * 4]) = o;
            }
            __syncwarp();
        }
        // no CTA barrier: Xs rows are warp-private, weights read-only
    }
}

extern "C" void kernel_launch(void* const* d_in, const int* in_sizes, int n_in,
                              void* d_out, int out_size)
{
    const float* x  = (const float*)d_in[0];
    const int*   an = (const int*)  d_in[1];
    const float* w0 = (const float*)d_in[2];
    const float* b0 = (const float*)d_in[3];
    const float* w1 = (const float*)d_in[4];
    const float* b1 = (const float*)d_in[5];
    const float* w2 = (const float*)d_in[6];
    const float* b2 = (const float*)d_in[7];
    float* out = (float*)d_out;

    static_assert(sizeof(Smem) < 48 * 1024, "smem too big");
    cudaFuncSetAttribute(bpnn_bf16_kernel,
                         cudaFuncAttributeMaxDynamicSharedMemorySize,
                         (int)sizeof(Smem));

    zero_out_kernel<<<1, BB>>>(out);

    bpnn_bf16_kernel<<<NN, THREADS, sizeof(Smem)>>>(x, an, w0, b0, w1, b1, w2, b2, out);
}